// round 9
// baseline (speedup 1.0000x reference)
#include <cuda_runtime.h>
#include <cstdint>

#define B_    8
#define CI_   512
#define CO_   256
#define HW_   64
#define YP_   136
#define YPP   (YP_ * YP_)
#define ZS_   128
#define NQUAD 65
#define NQ2   (NQUAD * NQUAD)                 // 4225
#define NTOT  (B_ * NQ2)                      // 33800 quads
#define MT_   128                             // M per CTA
#define NTILES ((NTOT + MT_ - 1) / MT_)       // 265
#define NCH   16

__device__ float g_wf[9 * 16 * 4 * 4 * 32 * 16];   // B frag layout: [tap][ch][kt][wn][lane][nt*2+reg]
__device__ float g_xr[B_ * CI_ * HW_ * HW_];       // tf32-rounded x copy
__device__ float g_y[B_ * CO_ * YPP];              // padded intermediate (pad stays 0)

__device__ __forceinline__ uint32_t f2tf32(float f) {   // RN-to-even tf32 bits
    uint32_t u = __float_as_uint(f);
    u = u + 0xFFFu + ((u >> 13) & 1u);
    return u & 0xFFFFE000u;
}
__device__ __forceinline__ uint32_t sm_u32(const void* p) {
    uint32_t a;
    asm("{ .reg .u64 t; cvta.to.shared.u64 t, %1; cvt.u32.u64 %0, t; }" : "=r"(a) : "l"(p));
    return a;
}

// D(16x8) += A(16x8) * B(8x8), tf32. a packed as (v0,v1,v2,v3)=((m,k),(m,k+4),(m+8,k),(m+8,k+4))
__device__ __forceinline__ void mma8(float* c, float4 a, float b0, float b1) {
    asm volatile(
        "mma.sync.aligned.m16n8k8.row.col.f32.tf32.tf32.f32 "
        "{%0,%1,%2,%3}, {%4,%5,%6,%7}, {%8,%9}, {%0,%1,%2,%3};"
        : "+f"(c[0]), "+f"(c[1]), "+f"(c[2]), "+f"(c[3])
        : "r"(__float_as_uint(a.x)), "r"(__float_as_uint(a.z)),
          "r"(__float_as_uint(a.y)), "r"(__float_as_uint(a.w)),
          "r"(__float_as_uint(b0)), "r"(__float_as_uint(b1)));
}

// ---------------- parity tables as constexpr functions ----------------
__host__ __device__ constexpr int pc_nt(int P) { return P == 0 ? 4 : (P == 3 ? 1 : 2); }
__host__ __device__ constexpr int pc_sh(int P, int j) {
    return P == 0 ? j
         : P == 1 ? (j == 0 ? 1 : 3)
         : P == 2 ? (j == 0 ? 2 : 3)
         : 3;
}
__host__ __device__ constexpr int pc_tp(int P, int j) {
    return P == 0 ? (j == 0 ? 0 : j == 1 ? 2 : j == 2 ? 6 : 8)
         : P == 1 ? (j == 0 ? 1 : 7)
         : P == 2 ? (j == 0 ? 3 : 5)
         : 4;
}

// ---------------- x -> tf32-rounded copy ----------------
__global__ void roundx_kernel(const float* __restrict__ x) {
    int i = blockIdx.x * 256 + threadIdx.x;
    float4 v = ((const float4*)x)[i];
    uint4 u;
    u.x = f2tf32(v.x); u.y = f2tf32(v.y); u.z = f2tf32(v.z); u.w = f2tf32(v.w);
    ((uint4*)g_xr)[i] = u;
}

// ---------------- prep: demodulate + flip + tf32-round, B fragment layout ----------------
__global__ void prep_kernel(const float* __restrict__ w) {
    __shared__ float red[256];
    const int o = blockIdx.x, tid = threadIdx.x;
    const float wsc = 1.0f / sqrtf((float)(CI_ * 9));
    const float* wo = w + o * (CI_ * 9);
    float s = 0.f;
    for (int idx = tid; idx < CI_ * 9; idx += 256) {
        float v = wo[idx] * wsc;
        s += v * v;
    }
    red[tid] = s;
    __syncthreads();
    for (int st = 128; st > 0; st >>= 1) {
        if (tid < st) red[tid] += red[tid + st];
        __syncthreads();
    }
    const float scale = wsc * rsqrtf(red[0] + 1e-6f);
    const int wn = o >> 6, c6 = o & 63, nt = c6 >> 3, cn = c6 & 7;
    for (int idx = tid; idx < CI_ * 9; idx += 256) {
        int i = idx / 9, t = idx % 9, kh = t / 3, kw = t % 3;
        float v = wo[i * 9 + (2 - kh) * 3 + (2 - kw)] * scale;       // spatial flip
        int ch = i >> 5, k5 = i & 31, kt = k5 >> 3, ck = k5 & 7;
        int lane = cn * 4 + (ck & 3), reg = ck >> 2;
        g_wf[(size_t)((((t * 16 + ch) * 4 + kt) * 4 + wn) * 32 + lane) * 16 + nt * 2 + reg]
            = __uint_as_float(f2tf32(v));
    }
}

// ---------------- transposed conv, one parity, TF32 mma.sync, cp.async double buffer ----------------
template <int P>
__global__ void __launch_bounds__(256, 1) conv_mma() {
    constexpr int NT = pc_nt(P);
    extern __shared__ float4 smA[];            // 2 bufs x NT tiles x 1024 float4 frag entries

    const int tid = threadIdx.x, lane = tid & 31, warp = tid >> 5;
    const int wm = warp >> 2, wn = warp & 3;
    const int nt0 = blockIdx.x * MT_;
    const uint32_t smb = sm_u32(smA);

    // ---- staging precompute ----
    uint32_t base[4][2][NT];
    uint32_t vmask = 0;
    int kOff0[4], eIdx[4];
#pragma unroll
    for (int i = 0; i < 4; i++) {
        const int e = tid + i * 256;
        const int mtkt = e >> 5, sl = e & 31;
        eIdx[i]  = e;
        kOff0[i] = ((mtkt & 3) * 8 + (sl & 3)) << 12;          // kl * 4096
        const int m0 = (mtkt >> 2) * 16 + (sl >> 2);
#pragma unroll
        for (int row = 0; row < 2; row++) {
            const int gm = nt0 + m0 + row * 8;
            const int b = gm / NQ2, r = gm - b * NQ2;
            const int qa = r / NQUAD, qb = r - qa * NQUAD;
            const bool mok = gm < NTOT;
#pragma unroll
            for (int s = 0; s < NT; s++) {
                const int sh = pc_sh(P, s);
                const int iy = qa - 1 + (sh >> 1), ix = qb - 1 + (sh & 1);
                const bool ok = mok && ((unsigned)iy < HW_) && ((unsigned)ix < HW_);
                base[i][row][s] = ok ? (uint32_t)((b * CI_) << 12) + (uint32_t)(iy * HW_ + ix) : 0u;
                if (ok) vmask |= 1u << ((i * 2 + row) * NT + s);
            }
        }
    }

    // stage chunk ch into buffer buf via 4B cp.async (zero-fill when masked)
    auto stage = [&](int ch, int buf) {
        const uint32_t cco = (uint32_t)ch << 17;               // ch*32*4096 elements
#pragma unroll
        for (int i = 0; i < 4; i++) {
#pragma unroll
            for (int s = 0; s < NT; s++) {
                const uint32_t dst0 = smb + (uint32_t)(((buf * NT + s) * 1024 + eIdx[i]) * 16);
#pragma unroll
                for (int c = 0; c < 4; c++) {
                    const int row = c >> 1;
                    uint32_t ok4 = ((vmask >> ((i * 2 + row) * NT + s)) & 1u) << 2;
                    const float* src = g_xr + base[i][row][s] + cco + kOff0[i] + ((c & 1) << 14);
                    asm volatile("cp.async.ca.shared.global [%0], [%1], 4, %2;"
                                 :: "r"(dst0 + c * 4), "l"(src), "r"(ok4) : "memory");
                }
            }
        }
        asm volatile("cp.async.commit_group;" ::: "memory");
    };

    float acc[4][8][4];
#pragma unroll
    for (int q = 0; q < 4; q++)
#pragma unroll
        for (int n = 0; n < 8; n++)
#pragma unroll
            for (int r = 0; r < 4; r++) acc[q][n][r] = 0.f;

    stage(0, 0);
    asm volatile("cp.async.wait_group 0;" ::: "memory");
    __syncthreads();

    for (int ch = 0; ch < NCH; ch++) {
        if (ch + 1 < NCH) stage(ch + 1, (ch + 1) & 1);         // async prefetch
        const int bo = (ch & 1) * NT;
        // ---- compute on current buffer ----
#pragma unroll
        for (int j = 0; j < NT; j++) {
            const int tap = pc_tp(P, j);
#pragma unroll
            for (int kt = 0; kt < 4; kt++) {
                float4 af[4];
#pragma unroll
                for (int q = 0; q < 4; q++)
                    af[q] = smA[(bo + j) * 1024 + ((wm * 4 + q) * 4 + kt) * 32 + lane];
                const float4* bp = (const float4*)&g_wf[
                    (size_t)((((tap * 16 + ch) * 4 + kt) * 4 + wn) * 32 + lane) * 16];
                float4 bf0 = bp[0], bf1 = bp[1], bf2 = bp[2], bf3 = bp[3];
#pragma unroll
                for (int q = 0; q < 4; q++) {
                    mma8(acc[q][0], af[q], bf0.x, bf0.y);
                    mma8(acc[q][1], af[q], bf0.z, bf0.w);
                    mma8(acc[q][2], af[q], bf1.x, bf1.y);
                    mma8(acc[q][3], af[q], bf1.z, bf1.w);
                    mma8(acc[q][4], af[q], bf2.x, bf2.y);
                    mma8(acc[q][5], af[q], bf2.z, bf2.w);
                    mma8(acc[q][6], af[q], bf3.x, bf3.y);
                    mma8(acc[q][7], af[q], bf3.z, bf3.w);
                }
            }
        }
        if (ch + 1 < NCH) {
            asm volatile("cp.async.wait_group 0;" ::: "memory");
            __syncthreads();
        }
    }

    // ---- epilogue: C frag -> g_y (parity pixel per quad) ----
#pragma unroll
    for (int q = 0; q < 4; q++) {
        size_t addr[2]; bool ok[2];
#pragma unroll
        for (int row = 0; row < 2; row++) {
            const int gm = nt0 + wm * 64 + q * 16 + (lane >> 2) + row * 8;
            const int b = gm / NQ2, r = gm - b * NQ2;
            const int qa = r / NQUAD, qb = r - qa * NQUAD;
            const int oy = 2 * qa + (P >> 1), ox = 2 * qb + (P & 1);
            ok[row] = (gm < NTOT) && (oy <= 128) && (ox <= 128);
            addr[row] = (size_t)(b * CO_) * YPP + (size_t)(oy + 1) * YP_ + (ox + 1);
        }
#pragma unroll
        for (int n = 0; n < 8; n++) {
            const int co = wn * 64 + n * 8 + 2 * (lane & 3);
            if (ok[0]) {
                size_t a0 = addr[0] + (size_t)co * YPP;
                g_y[a0] = acc[q][n][0];
                g_y[a0 + YPP] = acc[q][n][1];
            }
            if (ok[1]) {
                size_t a1 = addr[1] + (size_t)co * YPP;
                g_y[a1] = acc[q][n][2];
                g_y[a1 + YPP] = acc[q][n][3];
            }
        }
    }
}

// ---------------- depthwise 4x4 FIR blur, separable row-streaming ----------------
__global__ void blur_kernel(float* __restrict__ z) {
    const int cx = threadIdx.x;
    const int ry = threadIdx.y;
    const int bc = blockIdx.z;
    const int b = bc >> 8;
    const int col = bc & 255;
    const float* yb = g_y + (size_t)(b * CO_ + col) * YPP;
    float* zb = z + (size_t)(b * CO_ + col) * (ZS_ * ZS_);
    const int c0 = cx * 4;
    const int zy0 = ry * 16;

    float4 h0 = {}, h1 = {}, h2 = {};
#pragma unroll
    for (int k = 0; k < 19; k++) {
        const float* row = yb + (size_t)(zy0 + k) * YP_ + c0;
        float4 a = *(const float4*)row;
        float4 e = *(const float4*)(row + 4);
        float4 h;
        h.x = a.x + 3.f * a.y + 3.f * a.z + a.w;
        h.y = a.y + 3.f * a.z + 3.f * a.w + e.x;
        h.z = a.z + 3.f * a.w + 3.f * e.x + e.y;
        h.w = a.w + 3.f * e.x + 3.f * e.y + e.z;
        if (k >= 3) {
            float4 o;
            o.x = (h0.x + 3.f * h1.x + 3.f * h2.x + h.x) * 0.0625f;
            o.y = (h0.y + 3.f * h1.y + 3.f * h2.y + h.y) * 0.0625f;
            o.z = (h0.z + 3.f * h1.z + 3.f * h2.z + h.z) * 0.0625f;
            o.w = (h0.w + 3.f * h1.w + 3.f * h2.w + h.w) * 0.0625f;
            *(float4*)&zb[(size_t)(zy0 + k - 3) * ZS_ + c0] = o;
        }
        h0 = h1; h1 = h2; h2 = h;
    }
}

extern "C" void kernel_launch(void* const* d_in, const int* in_sizes, int n_in,
                              void* d_out, int out_size) {
    const float* x = (const float*)d_in[0];
    const float* w = (const float*)d_in[1];
    float* z = (float*)d_out;
    cudaFuncSetAttribute(conv_mma<0>, cudaFuncAttributeMaxDynamicSharedMemorySize, 2 * 4 * 16384);
    cudaFuncSetAttribute(conv_mma<1>, cudaFuncAttributeMaxDynamicSharedMemorySize, 2 * 2 * 16384);
    cudaFuncSetAttribute(conv_mma<2>, cudaFuncAttributeMaxDynamicSharedMemorySize, 2 * 2 * 16384);
    cudaFuncSetAttribute(conv_mma<3>, cudaFuncAttributeMaxDynamicSharedMemorySize, 2 * 1 * 16384);
    roundx_kernel<<<16384, 256>>>(x);
    prep_kernel<<<CO_, 256>>>(w);
    conv_mma<3><<<NTILES, 256, 2 * 1 * 16384>>>();
    conv_mma<0><<<NTILES, 256, 2 * 4 * 16384>>>();
    conv_mma<1><<<NTILES, 256, 2 * 2 * 16384>>>();
    conv_mma<2><<<NTILES, 256, 2 * 2 * 16384>>>();
    blur_kernel<<<dim3(1, 1, B_ * CO_), dim3(32, 8)>>>(z);
}

// round 10
// speedup vs baseline: 1.2729x; 1.2729x over previous
#include <cuda_runtime.h>
#include <cstdint>

#define B_    8
#define CI_   512
#define CO_   256
#define HW_   64
#define YP_   136
#define YPP   (YP_ * YP_)
#define ZS_   128
#define NQUAD 65
#define NQ2   (NQUAD * NQUAD)                 // 4225
#define NTOT  (B_ * NQ2)                      // 33800 quads
#define MT_   128                             // M per CTA
#define NTILES ((NTOT + MT_ - 1) / MT_)       // 265
#define NCH   16
#define CONV_SMEM (2 * (16384 + 32768))       // 96 KB: double-buffered A(16K) + B(32K)

// B frag layout: [tap][ch][kt][wn][p][lane][c]  (lane-major 16B granules -> conflict-free LDS.128)
__device__ float g_wf[9 * 16 * 4 * 4 * 4 * 32 * 4];
__device__ float g_xr[B_ * CI_ * HW_ * HW_];       // tf32-rounded x copy
__device__ float g_y[B_ * CO_ * YPP];              // padded intermediate (pad stays 0)

__device__ __forceinline__ uint32_t f2tf32(float f) {   // RN-to-even tf32 bits
    uint32_t u = __float_as_uint(f);
    u = u + 0xFFFu + ((u >> 13) & 1u);
    return u & 0xFFFFE000u;
}
__device__ __forceinline__ uint32_t sm_u32(const void* p) {
    uint32_t a;
    asm("{ .reg .u64 t; cvta.to.shared.u64 t, %1; cvt.u32.u64 %0, t; }" : "=r"(a) : "l"(p));
    return a;
}

// D(16x8) += A(16x8) * B(8x8), tf32. a packed as (v0,v1,v2,v3)=((m,k),(m,k+4),(m+8,k),(m+8,k+4))
__device__ __forceinline__ void mma8(float* c, float4 a, float b0, float b1) {
    asm volatile(
        "mma.sync.aligned.m16n8k8.row.col.f32.tf32.tf32.f32 "
        "{%0,%1,%2,%3}, {%4,%5,%6,%7}, {%8,%9}, {%0,%1,%2,%3};"
        : "+f"(c[0]), "+f"(c[1]), "+f"(c[2]), "+f"(c[3])
        : "r"(__float_as_uint(a.x)), "r"(__float_as_uint(a.z)),
          "r"(__float_as_uint(a.y)), "r"(__float_as_uint(a.w)),
          "r"(__float_as_uint(b0)), "r"(__float_as_uint(b1)));
}

// ---------------- parity tables as constexpr functions ----------------
__host__ __device__ constexpr int pc_nt(int P) { return P == 0 ? 4 : (P == 3 ? 1 : 2); }
__host__ __device__ constexpr int pc_sh(int P, int j) {
    return P == 0 ? j
         : P == 1 ? (j == 0 ? 1 : 3)
         : P == 2 ? (j == 0 ? 2 : 3)
         : 3;
}
__host__ __device__ constexpr int pc_tp(int P, int j) {
    return P == 0 ? (j == 0 ? 0 : j == 1 ? 2 : j == 2 ? 6 : 8)
         : P == 1 ? (j == 0 ? 1 : 7)
         : P == 2 ? (j == 0 ? 3 : 5)
         : 4;
}

// ---------------- x -> tf32-rounded copy ----------------
__global__ void roundx_kernel(const float* __restrict__ x) {
    int i = blockIdx.x * 256 + threadIdx.x;
    float4 v = ((const float4*)x)[i];
    uint4 u;
    u.x = f2tf32(v.x); u.y = f2tf32(v.y); u.z = f2tf32(v.z); u.w = f2tf32(v.w);
    ((uint4*)g_xr)[i] = u;
}

// ---------------- prep: demodulate + flip + tf32-round, B fragment layout ----------------
__global__ void prep_kernel(const float* __restrict__ w) {
    __shared__ float red[256];
    const int o = blockIdx.x, tid = threadIdx.x;
    const float wsc = 1.0f / sqrtf((float)(CI_ * 9));
    const float* wo = w + o * (CI_ * 9);
    float s = 0.f;
    for (int idx = tid; idx < CI_ * 9; idx += 256) {
        float v = wo[idx] * wsc;
        s += v * v;
    }
    red[tid] = s;
    __syncthreads();
    for (int st = 128; st > 0; st >>= 1) {
        if (tid < st) red[tid] += red[tid + st];
        __syncthreads();
    }
    const float scale = wsc * rsqrtf(red[0] + 1e-6f);
    const int wn = o >> 6, c6 = o & 63, nt = c6 >> 3, cn = c6 & 7;
    const int p = nt >> 1;
    for (int idx = tid; idx < CI_ * 9; idx += 256) {
        int i = idx / 9, t = idx % 9, kh = t / 3, kw = t % 3;
        float v = wo[i * 9 + (2 - kh) * 3 + (2 - kw)] * scale;       // spatial flip
        int ch = i >> 5, k5 = i & 31, kt = k5 >> 3, ck = k5 & 7;
        int lane = cn * 4 + (ck & 3), reg = ck >> 2;
        int c = (nt & 1) * 2 + reg;
        g_wf[(size_t)((((((t * 16 + ch) * 4 + kt) * 4 + wn) * 4 + p) * 32 + lane)) * 4 + c]
            = __uint_as_float(f2tf32(v));
    }
}

// ---------------- transposed conv, one parity, TF32 mma.sync, full smem pipeline ----------------
template <int P>
__global__ void __launch_bounds__(256, 1) conv_mma() {
    constexpr int NT = pc_nt(P);
    constexpr int S  = NCH * NT;               // steps: (ch, tap) pairs
    extern __shared__ float4 smem4[];
    float4* smA = smem4;                       // 2 bufs x 1024 float4 (A frag tile, one shift)
    float4* smB = smem4 + 2048;                // 2 bufs x 2048 float4 (B tap slice)
    const uint32_t smA_u = sm_u32(smA);
    const uint32_t smB_u = sm_u32(smB);

    const int tid = threadIdx.x, lane = tid & 31, warp = tid >> 5;
    const int wm = warp >> 2, wn = warp & 3;
    const int nt0 = blockIdx.x * MT_;

    // ---- staging precompute: per (i, row) quad coords ----
    int qa_[4][2], qb_[4][2];
    uint32_t bb_[4][2];
    bool mok_[4][2];
    int kOff0[4], eIdx[4];
#pragma unroll
    for (int i = 0; i < 4; i++) {
        const int e = tid + i * 256;
        const int mtkt = e >> 5, sl = e & 31;
        eIdx[i]  = e;
        kOff0[i] = ((mtkt & 3) * 8 + (sl & 3)) << 12;          // kl * 4096
        const int m0 = (mtkt >> 2) * 16 + (sl >> 2);
#pragma unroll
        for (int row = 0; row < 2; row++) {
            const int gm = nt0 + m0 + row * 8;
            const int b = gm / NQ2, r = gm - b * NQ2;
            qa_[i][row] = r / NQUAD;
            qb_[i][row] = r - qa_[i][row] * NQUAD;
            bb_[i][row] = (uint32_t)((b * CI_) << 12);
            mok_[i][row] = gm < NTOT;
        }
    }

    // stage step st into buffer buf: A (one shift, zfill OOB) + B (one tap slice, coalesced)
    auto stage = [&](int st, int buf) {
        const int ch = st / NT, j = st - ch * NT;
        const int sh = pc_sh(P, j);
        const int dy = sh >> 1, dx = sh & 1;
        const uint32_t cco = (uint32_t)ch << 17;
#pragma unroll
        for (int i = 0; i < 4; i++) {
            const uint32_t dst0 = smA_u + (uint32_t)((buf * 1024 + eIdx[i]) * 16);
#pragma unroll
            for (int row = 0; row < 2; row++) {
                const int iy = qa_[i][row] - 1 + dy, ix = qb_[i][row] - 1 + dx;
                const bool ok = mok_[i][row] && ((unsigned)iy < HW_) && ((unsigned)ix < HW_);
                const uint32_t okn = ok ? 4u : 0u;
                const float* src = g_xr + bb_[i][row] + (iy * HW_ + ix) + cco + kOff0[i];
                asm volatile("cp.async.ca.shared.global [%0], [%1], 4, %2;"
                             :: "r"(dst0 + row * 8), "l"(src), "r"(okn) : "memory");
                asm volatile("cp.async.ca.shared.global [%0], [%1], 4, %2;"
                             :: "r"(dst0 + row * 8 + 4), "l"(src + (1 << 14)), "r"(okn) : "memory");
            }
        }
        const int tap = pc_tp(P, j);
        const float4* bs = ((const float4*)g_wf) + (size_t)(tap * 16 + ch) * 2048 + tid;
        const uint32_t bd = smB_u + (uint32_t)((buf * 2048 + tid) * 16);
#pragma unroll
        for (int t = 0; t < 8; t++)
            asm volatile("cp.async.ca.shared.global [%0], [%1], 16;"
                         :: "r"(bd + t * 4096), "l"(bs + t * 256) : "memory");
        asm volatile("cp.async.commit_group;" ::: "memory");
    };

    float acc[4][8][4];
#pragma unroll
    for (int q = 0; q < 4; q++)
#pragma unroll
        for (int n = 0; n < 8; n++)
#pragma unroll
            for (int r = 0; r < 4; r++) acc[q][n][r] = 0.f;

    stage(0, 0);
    asm volatile("cp.async.wait_group 0;" ::: "memory");
    __syncthreads();

    for (int st = 0; st < S; st++) {
        if (st + 1 < S) stage(st + 1, (st + 1) & 1);           // async prefetch
        const int bo = (st & 1);
#pragma unroll
        for (int kt = 0; kt < 4; kt++) {
            float4 af[4], bf[4];
#pragma unroll
            for (int q = 0; q < 4; q++)
                af[q] = smA[bo * 1024 + ((wm * 4 + q) * 4 + kt) * 32 + lane];
#pragma unroll
            for (int p = 0; p < 4; p++)
                bf[p] = smB[bo * 2048 + ((kt * 4 + wn) * 4 + p) * 32 + lane];
#pragma unroll
            for (int q = 0; q < 4; q++) {
                mma8(acc[q][0], af[q], bf[0].x, bf[0].y);
                mma8(acc[q][1], af[q], bf[0].z, bf[0].w);
                mma8(acc[q][2], af[q], bf[1].x, bf[1].y);
                mma8(acc[q][3], af[q], bf[1].z, bf[1].w);
                mma8(acc[q][4], af[q], bf[2].x, bf[2].y);
                mma8(acc[q][5], af[q], bf[2].z, bf[2].w);
                mma8(acc[q][6], af[q], bf[3].x, bf[3].y);
                mma8(acc[q][7], af[q], bf[3].z, bf[3].w);
            }
        }
        if (st + 1 < S) {
            asm volatile("cp.async.wait_group 0;" ::: "memory");
            __syncthreads();
        }
    }

    // ---- epilogue: C frag -> g_y (parity pixel per quad) ----
#pragma unroll
    for (int q = 0; q < 4; q++) {
        size_t addr[2]; bool ok[2];
#pragma unroll
        for (int row = 0; row < 2; row++) {
            const int gm = nt0 + wm * 64 + q * 16 + (lane >> 2) + row * 8;
            const int b = gm / NQ2, r = gm - b * NQ2;
            const int qa = r / NQUAD, qb = r - qa * NQUAD;
            const int oy = 2 * qa + (P >> 1), ox = 2 * qb + (P & 1);
            ok[row] = (gm < NTOT) && (oy <= 128) && (ox <= 128);
            addr[row] = (size_t)(b * CO_) * YPP + (size_t)(oy + 1) * YP_ + (ox + 1);
        }
#pragma unroll
        for (int n = 0; n < 8; n++) {
            const int co = wn * 64 + n * 8 + 2 * (lane & 3);
            if (ok[0]) {
                size_t a0 = addr[0] + (size_t)co * YPP;
                g_y[a0] = acc[q][n][0];
                g_y[a0 + YPP] = acc[q][n][1];
            }
            if (ok[1]) {
                size_t a1 = addr[1] + (size_t)co * YPP;
                g_y[a1] = acc[q][n][2];
                g_y[a1 + YPP] = acc[q][n][3];
            }
        }
    }
}

// ---------------- depthwise 4x4 FIR blur, separable row-streaming ----------------
__global__ void blur_kernel(float* __restrict__ z) {
    const int cx = threadIdx.x;
    const int ry = threadIdx.y;
    const int bc = blockIdx.z;
    const int b = bc >> 8;
    const int col = bc & 255;
    const float* yb = g_y + (size_t)(b * CO_ + col) * YPP;
    float* zb = z + (size_t)(b * CO_ + col) * (ZS_ * ZS_);
    const int c0 = cx * 4;
    const int zy0 = ry * 16;

    float4 h0 = {}, h1 = {}, h2 = {};
#pragma unroll
    for (int k = 0; k < 19; k++) {
        const float* row = yb + (size_t)(zy0 + k) * YP_ + c0;
        float4 a = *(const float4*)row;
        float4 e = *(const float4*)(row + 4);
        float4 h;
        h.x = a.x + 3.f * a.y + 3.f * a.z + a.w;
        h.y = a.y + 3.f * a.z + 3.f * a.w + e.x;
        h.z = a.z + 3.f * a.w + 3.f * e.x + e.y;
        h.w = a.w + 3.f * e.x + 3.f * e.y + e.z;
        if (k >= 3) {
            float4 o;
            o.x = (h0.x + 3.f * h1.x + 3.f * h2.x + h.x) * 0.0625f;
            o.y = (h0.y + 3.f * h1.y + 3.f * h2.y + h.y) * 0.0625f;
            o.z = (h0.z + 3.f * h1.z + 3.f * h2.z + h.z) * 0.0625f;
            o.w = (h0.w + 3.f * h1.w + 3.f * h2.w + h.w) * 0.0625f;
            *(float4*)&zb[(size_t)(zy0 + k - 3) * ZS_ + c0] = o;
        }
        h0 = h1; h1 = h2; h2 = h;
    }
}

extern "C" void kernel_launch(void* const* d_in, const int* in_sizes, int n_in,
                              void* d_out, int out_size) {
    const float* x = (const float*)d_in[0];
    const float* w = (const float*)d_in[1];
    float* z = (float*)d_out;
    cudaFuncSetAttribute(conv_mma<0>, cudaFuncAttributeMaxDynamicSharedMemorySize, CONV_SMEM);
    cudaFuncSetAttribute(conv_mma<1>, cudaFuncAttributeMaxDynamicSharedMemorySize, CONV_SMEM);
    cudaFuncSetAttribute(conv_mma<2>, cudaFuncAttributeMaxDynamicSharedMemorySize, CONV_SMEM);
    cudaFuncSetAttribute(conv_mma<3>, cudaFuncAttributeMaxDynamicSharedMemorySize, CONV_SMEM);
    roundx_kernel<<<16384, 256>>>(x);
    prep_kernel<<<CO_, 256>>>(w);
    conv_mma<3><<<NTILES, 256, CONV_SMEM>>>();
    conv_mma<0><<<NTILES, 256, CONV_SMEM>>>();
    conv_mma<1><<<NTILES, 256, CONV_SMEM>>>();
    conv_mma<2><<<NTILES, 256, CONV_SMEM>>>();
    blur_kernel<<<dim3(1, 1, B_ * CO_), dim3(32, 8)>>>(z);
}